// round 1
// baseline (speedup 1.0000x reference)
#include <cuda_runtime.h>
#include <cstdint>
#include <cstddef>

// Problem constants (from reference): N=100000, E=1600000, F=128, H=64, C=40, G=2048
#define NMAX 100000
#define EMAX 1600000
#define GMAX 2048
#define HDIM 64

// ---------------- scratch (device globals; no runtime alloc allowed) ----------------
__device__ __align__(16) float g_h  [NMAX * HDIM];   // pre-MLP output
__device__ __align__(16) float g_hws[NMAX * HDIM];   // (h @ W) * isq, per layer
__device__ __align__(16) float g_agg[NMAX * HDIM];   // edge-aggregated sums
__device__ __align__(16) float g_h1 [NMAX * HDIM];   // layer-1 activations (needed for skip)
__device__ __align__(16) float g_deg[NMAX];          // degree -> isq (in place)
__device__ __align__(16) float g_readout[GMAX * HDIM];
__device__ int g_idx32;                              // 1 if indices are int32, 0 if int64

// ---------------- index dtype detection (device-side, capture-safe) ----------------
__global__ void k_detect(const long long* e, int cnt, long long nlim) {
    int f = 0;
    for (int i = 0; i < cnt; i++) {
        long long v = e[i];
        if (v < 0 || v >= nlim) { f = 1; break; }
    }
    g_idx32 = f;
}

__device__ __forceinline__ int load_idx(const void* p, int i) {
    if (g_idx32) return ((const int*)p)[i];
    return (int)((const long long*)p)[i];
}

// ---------------- zero scratch ----------------
__global__ void k_zero_all(int n, int g) {
    int i = blockIdx.x * blockDim.x + threadIdx.x;
    float4 z = make_float4(0.f, 0.f, 0.f, 0.f);
    if (i < n * 16) ((float4*)g_agg)[i] = z;
    if (i < n)      g_deg[i] = 0.f;
    if (i < g * 16) ((float4*)g_readout)[i] = z;
}

// ---------------- degree + isq ----------------
__global__ void k_deg(const void* eidx, int E) {
    int e = blockIdx.x * blockDim.x + threadIdx.x;
    if (e >= E) return;
    int dst = load_idx(eidx, E + e);
    atomicAdd(&g_deg[dst], 1.0f);
}

__global__ void k_isq(int n) {
    int i = blockIdx.x * blockDim.x + threadIdx.x;
    if (i < n) g_deg[i] = rsqrtf(g_deg[i] + 1.0f);
}

// ---------------- row GEMM: out[n, 64] = A[n, K] @ W[K, 64] (+bias) (*isq) ----------------
// 128 threads/block, one node per thread, 64 accumulators (16 x float4).
// W staged in SMEM (broadcast reads), A tile staged in SMEM (coalesced LDG).
template<int K>
__global__ void __launch_bounds__(128) k_gemm(const float* __restrict__ A,
                                              const float* __restrict__ W,
                                              const float* __restrict__ bias,
                                              const float* __restrict__ isq,
                                              float* __restrict__ out, int n) {
    __shared__ float4 Ws[K * 16];     // K x 64 floats
    __shared__ float  As[128 * 17];   // 128 nodes x 16 k, padded

    for (int i = threadIdx.x; i < K * 16; i += 128)
        Ws[i] = reinterpret_cast<const float4*>(W)[i];

    float4 acc[16];
#pragma unroll
    for (int j = 0; j < 16; j++) acc[j] = make_float4(0.f, 0.f, 0.f, 0.f);

    int node = blockIdx.x * 128 + threadIdx.x;

    for (int k0 = 0; k0 < K; k0 += 16) {
        __syncthreads();
#pragma unroll
        for (int i = 0; i < 16; i++) {
            int idx = i * 128 + threadIdx.x;
            int nn = idx >> 4, kk = idx & 15;
            int gn = blockIdx.x * 128 + nn;
            As[nn * 17 + kk] = (gn < n) ? A[(size_t)gn * K + k0 + kk] : 0.f;
        }
        __syncthreads();
#pragma unroll
        for (int kk = 0; kk < 16; kk++) {
            float a = As[threadIdx.x * 17 + kk];
            const float4* wr = &Ws[(k0 + kk) * 16];
#pragma unroll
            for (int j = 0; j < 16; j++) {
                float4 w = wr[j];
                acc[j].x = fmaf(a, w.x, acc[j].x);
                acc[j].y = fmaf(a, w.y, acc[j].y);
                acc[j].z = fmaf(a, w.z, acc[j].z);
                acc[j].w = fmaf(a, w.w, acc[j].w);
            }
        }
    }

    if (node < n) {
        float s = isq ? isq[node] : 1.0f;
        float4* o = reinterpret_cast<float4*>(out) + (size_t)node * 16;
#pragma unroll
        for (int j = 0; j < 16; j++) {
            float4 v = acc[j];
            if (bias) {
                float4 b = reinterpret_cast<const float4*>(bias)[j];
                v.x += b.x; v.y += b.y; v.z += b.z; v.w += b.w;
            }
            v.x *= s; v.y *= s; v.z *= s; v.w *= s;
            o[j] = v;
        }
    }
}

// ---------------- edge scatter: agg[dst] += hws[src], 16 threads/edge, float4 atomics ----------------
__global__ void k_scatter(const void* __restrict__ eidx, int E) {
    int t = blockIdx.x * blockDim.x + threadIdx.x;
    int e = t >> 4;
    if (e >= E) return;
    int lane = t & 15;
    int src, dst;
    if (g_idx32) {
        const int* p = (const int*)eidx;
        src = p[e]; dst = p[E + e];
    } else {
        const long long* p = (const long long*)eidx;
        src = (int)p[e]; dst = (int)p[E + e];
    }
    float4 v = ((const float4*)g_hws)[(size_t)src * 16 + lane];
    atomicAdd(((float4*)g_agg) + (size_t)dst * 16 + lane, v);
}

// ---------------- finalize: v = isq*(agg+hws)+bias; LN; ReLU; [skip + readout pool] ----------------
// One warp per node, float2 per lane, shuffle reductions. Resets agg to 0.
__global__ void k_finalize(const float* __restrict__ bias,
                           const float* __restrict__ lng, const float* __restrict__ lnb,
                           float* __restrict__ outh, int n,
                           int do_readout, const void* __restrict__ batch) {
    int t = blockIdx.x * blockDim.x + threadIdx.x;
    int node = t >> 5, lane = t & 31;
    if (node >= n) return;

    float s = g_deg[node];  // holds isq
    size_t off = (size_t)node * 32 + lane;
    float2 a  = ((float2*)g_agg)[off];
    float2 hv = ((const float2*)g_hws)[off];
    ((float2*)g_agg)[off] = make_float2(0.f, 0.f);  // reset for next use

    float2 bb = ((const float2*)bias)[lane];
    float vx = fmaf(s, a.x + hv.x, bb.x);
    float vy = fmaf(s, a.y + hv.y, bb.y);

    float sum = vx + vy;
#pragma unroll
    for (int o = 16; o; o >>= 1) sum += __shfl_xor_sync(0xffffffffu, sum, o);
    float mu = sum * (1.0f / 64.0f);

    float dx = vx - mu, dy = vy - mu;
    float var = dx * dx + dy * dy;
#pragma unroll
    for (int o = 16; o; o >>= 1) var += __shfl_xor_sync(0xffffffffu, var, o);
    float rstd = rsqrtf(var * (1.0f / 64.0f) + 1e-5f);

    float2 gg = ((const float2*)lng)[lane];
    float2 lb = ((const float2*)lnb)[lane];
    float ox = fmaxf(fmaf(dx * rstd, gg.x, lb.x), 0.f);
    float oy = fmaxf(fmaf(dy * rstd, gg.y, lb.y), 0.f);

    if (!do_readout) {
        ((float2*)outh)[off] = make_float2(ox, oy);
    } else {
        float2 h1v = ((const float2*)g_h1)[off];
        float2 sk = make_float2(ox + h1v.x, oy + h1v.y);
        int grp = load_idx(batch, node);
        atomicAdd(((float2*)g_readout) + (size_t)grp * 32 + lane, sk);
    }
}

// ---------------- post GEMM: out[G, 40] = readout[G, 64] @ post_w[64, 40] + post_b ----------------
__global__ void k_post(const float* __restrict__ W, const float* __restrict__ b,
                       float* __restrict__ out, int G) {
    __shared__ float r[64];
    int g = blockIdx.x;
    r[threadIdx.x] = g_readout[(size_t)g * 64 + threadIdx.x];
    __syncthreads();
    int c = threadIdx.x;
    if (c < 40) {
        float acc = b[c];
#pragma unroll
        for (int k = 0; k < 64; k++) acc = fmaf(r[k], __ldg(&W[k * 40 + c]), acc);
        out[(size_t)g * 40 + c] = acc;
    }
}

// ---------------- launch ----------------
extern "C" void kernel_launch(void* const* d_in, const int* in_sizes, int n_in,
                              void* d_out, int out_size) {
    const float* x      = (const float*)d_in[0];
    const void*  eidx   = d_in[1];
    const void*  batch  = d_in[2];
    const float* pre_w  = (const float*)d_in[3];
    const float* pre_b  = (const float*)d_in[4];
    const float* c1_w   = (const float*)d_in[5];
    const float* c1_b   = (const float*)d_in[6];
    const float* n1_g   = (const float*)d_in[7];
    const float* n1_b   = (const float*)d_in[8];
    const float* c2_w   = (const float*)d_in[9];
    const float* c2_b   = (const float*)d_in[10];
    const float* n2_g   = (const float*)d_in[11];
    const float* n2_b   = (const float*)d_in[12];
    const float* post_w = (const float*)d_in[13];
    const float* post_b = (const float*)d_in[14];

    int N = in_sizes[0] / 128;
    int E = in_sizes[1] / 2;
    int G = out_size / 40;

    float *p_h, *p_hws_unused, *p_h1, *p_isq;
    cudaGetSymbolAddress((void**)&p_h,   g_h);
    cudaGetSymbolAddress((void**)&p_hws_unused, g_hws);
    cudaGetSymbolAddress((void**)&p_h1,  g_h1);
    cudaGetSymbolAddress((void**)&p_isq, g_deg);
    float* p_hws = p_hws_unused;

    int dcnt = 2 * E < 1024 ? 2 * E : 1024;
    k_detect<<<1, 1>>>((const long long*)eidx, dcnt, (long long)N);

    k_zero_all<<<(N * 16 + 255) / 256, 256>>>(N, G);

    k_deg<<<(E + 255) / 256, 256>>>(eidx, E);
    k_isq<<<(N + 255) / 256, 256>>>(N);

    // pre-MLP: h = x @ pre_w + pre_b
    k_gemm<128><<<(N + 127) / 128, 128>>>(x, pre_w, pre_b, nullptr, p_h, N);

    // layer 1
    k_gemm<64><<<(N + 127) / 128, 128>>>(p_h, c1_w, nullptr, p_isq, p_hws, N);
    k_scatter<<<((size_t)E * 16 + 255) / 256, 256>>>(eidx, E);
    k_finalize<<<(N * 32 + 255) / 256, 256>>>(c1_b, n1_g, n1_b, p_h1, N, 0, nullptr);

    // layer 2 (+ skip + readout pooling fused)
    k_gemm<64><<<(N + 127) / 128, 128>>>(p_h1, c2_w, nullptr, p_isq, p_hws, N);
    k_scatter<<<((size_t)E * 16 + 255) / 256, 256>>>(eidx, E);
    k_finalize<<<(N * 32 + 255) / 256, 256>>>(c2_b, n2_g, n2_b, nullptr, N, 1, batch);

    // post: out = readout @ post_w + post_b
    k_post<<<G, 64>>>(post_w, post_b, (float*)d_out, G);
}

// round 2
// speedup vs baseline: 1.2860x; 1.2860x over previous
#include <cuda_runtime.h>
#include <cstdint>
#include <cstddef>

// Problem constants: N=100000, E=1600000, F=128, H=64, C=40, G=2048
#define NMAX 100000
#define EMAX 1600000
#define GMAX 2048
#define HDIM 64

// ---------------- scratch (device globals; no runtime alloc allowed) ----------------
__device__ __align__(16) float g_h  [NMAX * HDIM];   // pre-MLP output
__device__ __align__(16) float g_hws[NMAX * HDIM];   // (h @ W) * isq, per layer
__device__ __align__(16) float g_h1 [NMAX * HDIM];   // layer-1 activations (for skip)
__device__ __align__(16) float g_deg[NMAX];          // isq
__device__ __align__(16) float g_readout[GMAX * HDIM];
__device__ __align__(16) int   g_cnt[NMAX];          // per-dst degree (int)
__device__ __align__(16) int   g_ptr[NMAX];          // CSR row starts (exclusive scan)
__device__ __align__(16) int   g_cursor[NMAX];       // fill cursors
__device__ __align__(16) int   g_csr_src[EMAX];      // CSR column (src) indices
__device__ int g_bsum[256];                          // scan block sums
__device__ int g_idx32;                              // 1 if indices are int32

// ---------------- index dtype detection (device-side, capture-safe) ----------------
__global__ void k_detect(const long long* e, int cnt, long long nlim) {
    int f = 0;
    for (int i = 0; i < cnt; i++) {
        long long v = e[i];
        if (v < 0 || v >= nlim) { f = 1; break; }
    }
    g_idx32 = f;
}

__device__ __forceinline__ int load_idx(const void* p, int i) {
    if (g_idx32) return ((const int*)p)[i];
    return (int)((const long long*)p)[i];
}

// ---------------- zero: cnt + readout ----------------
__global__ void k_zero(int n, int g) {
    int i = blockIdx.x * blockDim.x + threadIdx.x;
    if (i < n) g_cnt[i] = 0;
    if (i < g * 16) ((float4*)g_readout)[i] = make_float4(0.f, 0.f, 0.f, 0.f);
}

// ---------------- degree histogram ----------------
__global__ void k_hist(const void* __restrict__ eidx, int E) {
    int e = blockIdx.x * blockDim.x + threadIdx.x;
    if (e >= E) return;
    int dst = load_idx(eidx, E + e);
    atomicAdd(&g_cnt[dst], 1);
}

// ---------------- exclusive scan of g_cnt -> g_ptr (3 kernels) ----------------
__global__ void __launch_bounds__(256) k_scan1(int n) {
    __shared__ int wsum[8];
    int base = blockIdx.x * 1024 + threadIdx.x * 4;
    int c0 = 0, c1 = 0, c2 = 0, c3 = 0;
    if (base + 3 < n) {
        int4 c = *(const int4*)&g_cnt[base];
        c0 = c.x; c1 = c.y; c2 = c.z; c3 = c.w;
    } else if (base < n) {
        c0 = g_cnt[base];
        if (base + 1 < n) c1 = g_cnt[base + 1];
        if (base + 2 < n) c2 = g_cnt[base + 2];
    }
    int tot = c0 + c1 + c2 + c3;
    int lane = threadIdx.x & 31, wid = threadIdx.x >> 5;
    int v = tot;
#pragma unroll
    for (int o = 1; o < 32; o <<= 1) {
        int u = __shfl_up_sync(0xffffffffu, v, o);
        if (lane >= o) v += u;
    }
    if (lane == 31) wsum[wid] = v;
    __syncthreads();
    if (threadIdx.x == 0) {
        int s = 0;
        for (int i = 0; i < 8; i++) { int t = wsum[i]; wsum[i] = s; s += t; }
        g_bsum[blockIdx.x] = s;
    }
    __syncthreads();
    int excl = v - tot + wsum[wid];
    if (base < n) {
        g_ptr[base] = excl;
        if (base + 1 < n) g_ptr[base + 1] = excl + c0;
        if (base + 2 < n) g_ptr[base + 2] = excl + c0 + c1;
        if (base + 3 < n) g_ptr[base + 3] = excl + c0 + c1 + c2;
    }
}

__global__ void k_scan2(int nb) {   // 1 block, 128 threads, nb <= 128
    __shared__ int ws[4];
    int t = threadIdx.x;
    int v0 = (t < nb) ? g_bsum[t] : 0;
    int v = v0;
    int lane = t & 31, wid = t >> 5;
#pragma unroll
    for (int o = 1; o < 32; o <<= 1) {
        int u = __shfl_up_sync(0xffffffffu, v, o);
        if (lane >= o) v += u;
    }
    if (lane == 31) ws[wid] = v;
    __syncthreads();
    if (t == 0) {
        int s = 0;
        for (int i = 0; i < 4; i++) { int x = ws[i]; ws[i] = s; s += x; }
    }
    __syncthreads();
    int incl = v + ws[wid];
    if (t < nb) g_bsum[t] = incl - v0;  // exclusive
}

__global__ void k_scan3(int n) {    // add block offsets; init cursor + isq
    int i = blockIdx.x * blockDim.x + threadIdx.x;
    if (i >= n) return;
    int p = g_ptr[i] + g_bsum[i >> 10];
    g_ptr[i] = p;
    g_cursor[i] = p;
    g_deg[i] = rsqrtf((float)g_cnt[i] + 1.0f);
}

// ---------------- CSR fill ----------------
__global__ void k_fill(const void* __restrict__ eidx, int E) {
    int e = blockIdx.x * blockDim.x + threadIdx.x;
    if (e >= E) return;
    int src = load_idx(eidx, e);
    int dst = load_idx(eidx, E + e);
    int pos = atomicAdd(&g_cursor[dst], 1);
    g_csr_src[pos] = src;
}

// ---------------- row GEMM with packed f32x2 FMA ----------------
// out[n,64] = A[n,K] @ W[K,64] (+bias) (*isq). 128 thr/block, node per thread.
template<int K>
__global__ void __launch_bounds__(128) k_gemm(const float* __restrict__ A,
                                              const float* __restrict__ W,
                                              const float* __restrict__ bias,
                                              const float* __restrict__ isq,
                                              float* __restrict__ out, int n) {
    __shared__ float4 Ws[K * 16];     // K x 64 floats
    __shared__ float  As[128 * 17];   // 128 nodes x 16 k, padded

    for (int i = threadIdx.x; i < K * 16; i += 128)
        Ws[i] = reinterpret_cast<const float4*>(W)[i];

    unsigned long long acc[32];       // 64 outputs as 32 packed f32x2
#pragma unroll
    for (int j = 0; j < 32; j++) acc[j] = 0ULL;

    int node = blockIdx.x * 128 + threadIdx.x;

    for (int k0 = 0; k0 < K; k0 += 16) {
        __syncthreads();
#pragma unroll
        for (int i = 0; i < 16; i++) {
            int idx = i * 128 + threadIdx.x;
            int nn = idx >> 4, kk = idx & 15;
            int gn = blockIdx.x * 128 + nn;
            As[nn * 17 + kk] = (gn < n) ? A[(size_t)gn * K + k0 + kk] : 0.f;
        }
        __syncthreads();
#pragma unroll
        for (int kk = 0; kk < 16; kk++) {
            float a = As[threadIdx.x * 17 + kk];
            unsigned long long a2;
            asm("mov.b64 %0, {%1, %1};" : "=l"(a2) : "f"(a));
            const float4* wr = &Ws[(k0 + kk) * 16];
#pragma unroll
            for (int j = 0; j < 16; j++) {
                float4 w = wr[j];
                unsigned long long w0, w1;
                asm("mov.b64 %0, {%1, %2};" : "=l"(w0) : "f"(w.x), "f"(w.y));
                asm("mov.b64 %0, {%1, %2};" : "=l"(w1) : "f"(w.z), "f"(w.w));
                asm("fma.rn.f32x2 %0, %1, %2, %0;" : "+l"(acc[2 * j])     : "l"(a2), "l"(w0));
                asm("fma.rn.f32x2 %0, %1, %2, %0;" : "+l"(acc[2 * j + 1]) : "l"(a2), "l"(w1));
            }
        }
    }

    if (node < n) {
        float s = isq ? isq[node] : 1.0f;
        float2* o = reinterpret_cast<float2*>(out) + (size_t)node * 32;
#pragma unroll
        for (int j = 0; j < 32; j++) {
            float lo, hi;
            asm("mov.b64 {%0, %1}, %2;" : "=f"(lo), "=f"(hi) : "l"(acc[j]));
            if (bias) {
                float2 b = reinterpret_cast<const float2*>(bias)[j];
                lo += b.x; hi += b.y;
            }
            o[j] = make_float2(lo * s, hi * s);
        }
    }
}

// ---------------- fused gather + self + bias + LN + ReLU (+skip+readout) ----------------
// One warp per node. agg = sum over CSR row of hws[src] + hws[node] (self).
__global__ void __launch_bounds__(256) k_gather(const float* __restrict__ bias,
                                                const float* __restrict__ lng,
                                                const float* __restrict__ lnb,
                                                float* __restrict__ outh, int n,
                                                int do_readout,
                                                const void* __restrict__ batch) {
    int t = blockIdx.x * blockDim.x + threadIdx.x;
    int node = t >> 5, lane = t & 31;
    if (node >= n) return;

    int start = g_ptr[node];
    int cnt   = g_cnt[node];
    size_t off = (size_t)node * 32 + lane;
    const float2* hws2 = (const float2*)g_hws;

    float2 acc0 = hws2[off];  // self-loop term
    float2 acc1 = make_float2(0.f, 0.f);

    int j = 0;
    for (; j + 1 < cnt; j += 2) {
        int s0 = g_csr_src[start + j];
        int s1 = g_csr_src[start + j + 1];
        float2 v0 = hws2[(size_t)s0 * 32 + lane];
        float2 v1 = hws2[(size_t)s1 * 32 + lane];
        acc0.x += v0.x; acc0.y += v0.y;
        acc1.x += v1.x; acc1.y += v1.y;
    }
    if (j < cnt) {
        int s = g_csr_src[start + j];
        float2 v = hws2[(size_t)s * 32 + lane];
        acc0.x += v.x; acc0.y += v.y;
    }

    float s = g_deg[node];  // isq
    float2 bb = ((const float2*)bias)[lane];
    float vx = fmaf(s, acc0.x + acc1.x, bb.x);
    float vy = fmaf(s, acc0.y + acc1.y, bb.y);

    float sum = vx + vy;
#pragma unroll
    for (int o = 16; o; o >>= 1) sum += __shfl_xor_sync(0xffffffffu, sum, o);
    float mu = sum * (1.0f / 64.0f);

    float dx = vx - mu, dy = vy - mu;
    float var = dx * dx + dy * dy;
#pragma unroll
    for (int o = 16; o; o >>= 1) var += __shfl_xor_sync(0xffffffffu, var, o);
    float rstd = rsqrtf(var * (1.0f / 64.0f) + 1e-5f);

    float2 gg = ((const float2*)lng)[lane];
    float2 lb = ((const float2*)lnb)[lane];
    float ox = fmaxf(fmaf(dx * rstd, gg.x, lb.x), 0.f);
    float oy = fmaxf(fmaf(dy * rstd, gg.y, lb.y), 0.f);

    if (!do_readout) {
        ((float2*)outh)[off] = make_float2(ox, oy);
    } else {
        float2 h1v = ((const float2*)g_h1)[off];
        float2 sk = make_float2(ox + h1v.x, oy + h1v.y);
        int grp = load_idx(batch, node);
        atomicAdd(((float2*)g_readout) + (size_t)grp * 32 + lane, sk);
    }
}

// ---------------- post GEMM: out[G,40] = readout[G,64] @ post_w[64,40] + post_b ----------------
__global__ void k_post(const float* __restrict__ W, const float* __restrict__ b,
                       float* __restrict__ out, int G) {
    __shared__ float r[64];
    int g = blockIdx.x;
    r[threadIdx.x] = g_readout[(size_t)g * 64 + threadIdx.x];
    __syncthreads();
    int c = threadIdx.x;
    if (c < 40) {
        float acc = b[c];
#pragma unroll
        for (int k = 0; k < 64; k++) acc = fmaf(r[k], __ldg(&W[k * 40 + c]), acc);
        out[(size_t)g * 40 + c] = acc;
    }
}

// ---------------- launch ----------------
extern "C" void kernel_launch(void* const* d_in, const int* in_sizes, int n_in,
                              void* d_out, int out_size) {
    const float* x      = (const float*)d_in[0];
    const void*  eidx   = d_in[1];
    const void*  batch  = d_in[2];
    const float* pre_w  = (const float*)d_in[3];
    const float* pre_b  = (const float*)d_in[4];
    const float* c1_w   = (const float*)d_in[5];
    const float* c1_b   = (const float*)d_in[6];
    const float* n1_g   = (const float*)d_in[7];
    const float* n1_b   = (const float*)d_in[8];
    const float* c2_w   = (const float*)d_in[9];
    const float* c2_b   = (const float*)d_in[10];
    const float* n2_g   = (const float*)d_in[11];
    const float* n2_b   = (const float*)d_in[12];
    const float* post_w = (const float*)d_in[13];
    const float* post_b = (const float*)d_in[14];

    int N = in_sizes[0] / 128;
    int E = in_sizes[1] / 2;
    int G = out_size / 40;

    float *p_h, *p_hws, *p_h1, *p_isq;
    cudaGetSymbolAddress((void**)&p_h,   g_h);
    cudaGetSymbolAddress((void**)&p_hws, g_hws);
    cudaGetSymbolAddress((void**)&p_h1,  g_h1);
    cudaGetSymbolAddress((void**)&p_isq, g_deg);

    int dcnt = 2 * E < 1024 ? 2 * E : 1024;
    k_detect<<<1, 1>>>((const long long*)eidx, dcnt, (long long)N);

    // zero counters + readout
    int zmax = (N > G * 16) ? N : G * 16;
    k_zero<<<(zmax + 255) / 256, 256>>>(N, G);

    // CSR build: histogram -> scan -> fill (also computes isq)
    k_hist<<<(E + 255) / 256, 256>>>(eidx, E);
    int nb = (N + 1023) / 1024;
    k_scan1<<<nb, 256>>>(N);
    k_scan2<<<1, 128>>>(nb);
    k_scan3<<<(N + 255) / 256, 256>>>(N);
    k_fill<<<(E + 255) / 256, 256>>>(eidx, E);

    // pre-MLP: h = x @ pre_w + pre_b
    k_gemm<128><<<(N + 127) / 128, 128>>>(x, pre_w, pre_b, nullptr, p_h, N);

    // layer 1: hws = (h @ c1_w) * isq; fused gather+LN+ReLU -> h1
    k_gemm<64><<<(N + 127) / 128, 128>>>(p_h, c1_w, nullptr, p_isq, p_hws, N);
    k_gather<<<((size_t)N * 32 + 255) / 256, 256>>>(c1_b, n1_g, n1_b, p_h1, N, 0, nullptr);

    // layer 2: fused gather+LN+ReLU+skip+readout pooling
    k_gemm<64><<<(N + 127) / 128, 128>>>(p_h1, c2_w, nullptr, p_isq, p_hws, N);
    k_gather<<<((size_t)N * 32 + 255) / 256, 256>>>(c2_b, n2_g, n2_b, nullptr, N, 1, batch);

    // post: out = readout @ post_w + post_b
    k_post<<<G, 64>>>(post_w, post_b, (float*)d_out, G);
}

// round 3
// speedup vs baseline: 1.3938x; 1.0838x over previous
#include <cuda_runtime.h>
#include <cstdint>
#include <cstddef>

// Problem constants: N=100000, E=1600000, F=128, H=64, C=40, G=2048
#define NMAX 100000
#define EMAX 1600000
#define GMAX 2048
#define HDIM 64

// ---------------- scratch (device globals; no runtime alloc allowed) ----------------
__device__ __align__(16) float g_h  [NMAX * HDIM];   // pre-MLP output
__device__ __align__(16) float g_hws[NMAX * HDIM];   // (h @ W) * isq, per layer
__device__ __align__(16) float g_h1 [NMAX * HDIM];   // layer-1 activations (for skip)
__device__ __align__(16) float g_deg[NMAX];          // isq
__device__ __align__(16) float g_readout[GMAX * HDIM];
__device__ __align__(16) int   g_cnt[NMAX];          // per-dst degree
__device__ __align__(16) int   g_ptr[NMAX];          // CSR row starts
__device__ __align__(16) int   g_cursor[NMAX];       // fill cursors
__device__ __align__(16) int   g_csr_src[EMAX];      // CSR column (src) indices
__device__ int g_bsum[256];
__device__ int g_idx32;

// ---------------- index dtype detection (parallel, capture-safe) ----------------
__global__ void k_detect(const long long* e, int cnt, long long nlim) {
    int i = threadIdx.x;
    int f = 0;
    if (i < cnt) {
        long long v = e[i];
        f = (v < 0 || v >= nlim) ? 1 : 0;
    }
    int r = __syncthreads_or(f);
    if (i == 0) g_idx32 = r;
}

__device__ __forceinline__ int load_idx(const void* p, int i) {
    if (g_idx32) return ((const int*)p)[i];
    return (int)((const long long*)p)[i];
}

// ---------------- zero: cnt + readout ----------------
__global__ void k_zero(int n, int g) {
    int i = blockIdx.x * blockDim.x + threadIdx.x;
    if (i < n) g_cnt[i] = 0;
    if (i < g * 16) ((float4*)g_readout)[i] = make_float4(0.f, 0.f, 0.f, 0.f);
}

// ---------------- degree histogram ----------------
__global__ void k_hist(const void* __restrict__ eidx, int E) {
    int e = blockIdx.x * blockDim.x + threadIdx.x;
    if (e >= E) return;
    int dst = load_idx(eidx, E + e);
    atomicAdd(&g_cnt[dst], 1);
}

// ---------------- exclusive scan of g_cnt -> g_ptr (3 kernels) ----------------
__global__ void __launch_bounds__(256) k_scan1(int n) {
    __shared__ int wsum[8];
    int base = blockIdx.x * 1024 + threadIdx.x * 4;
    int c0 = 0, c1 = 0, c2 = 0, c3 = 0;
    if (base + 3 < n) {
        int4 c = *(const int4*)&g_cnt[base];
        c0 = c.x; c1 = c.y; c2 = c.z; c3 = c.w;
    } else if (base < n) {
        c0 = g_cnt[base];
        if (base + 1 < n) c1 = g_cnt[base + 1];
        if (base + 2 < n) c2 = g_cnt[base + 2];
    }
    int tot = c0 + c1 + c2 + c3;
    int lane = threadIdx.x & 31, wid = threadIdx.x >> 5;
    int v = tot;
#pragma unroll
    for (int o = 1; o < 32; o <<= 1) {
        int u = __shfl_up_sync(0xffffffffu, v, o);
        if (lane >= o) v += u;
    }
    if (lane == 31) wsum[wid] = v;
    __syncthreads();
    if (threadIdx.x == 0) {
        int s = 0;
        for (int i = 0; i < 8; i++) { int t = wsum[i]; wsum[i] = s; s += t; }
        g_bsum[blockIdx.x] = s;
    }
    __syncthreads();
    int excl = v - tot + wsum[wid];
    if (base < n) {
        g_ptr[base] = excl;
        if (base + 1 < n) g_ptr[base + 1] = excl + c0;
        if (base + 2 < n) g_ptr[base + 2] = excl + c0 + c1;
        if (base + 3 < n) g_ptr[base + 3] = excl + c0 + c1 + c2;
    }
}

__global__ void k_scan2(int nb) {   // 1 block, 128 threads, nb <= 128
    __shared__ int ws[4];
    int t = threadIdx.x;
    int v0 = (t < nb) ? g_bsum[t] : 0;
    int v = v0;
    int lane = t & 31, wid = t >> 5;
#pragma unroll
    for (int o = 1; o < 32; o <<= 1) {
        int u = __shfl_up_sync(0xffffffffu, v, o);
        if (lane >= o) v += u;
    }
    if (lane == 31) ws[wid] = v;
    __syncthreads();
    if (t == 0) {
        int s = 0;
        for (int i = 0; i < 4; i++) { int x = ws[i]; ws[i] = s; s += x; }
    }
    __syncthreads();
    int incl = v + ws[wid];
    if (t < nb) g_bsum[t] = incl - v0;
}

__global__ void k_scan3(int n) {    // add block offsets; init cursor + isq
    int i = blockIdx.x * blockDim.x + threadIdx.x;
    if (i >= n) return;
    int p = g_ptr[i] + g_bsum[i >> 10];
    g_ptr[i] = p;
    g_cursor[i] = p;
    g_deg[i] = rsqrtf((float)g_cnt[i] + 1.0f);
}

// ---------------- CSR fill ----------------
__global__ void k_fill(const void* __restrict__ eidx, int E) {
    int e = blockIdx.x * blockDim.x + threadIdx.x;
    if (e >= E) return;
    int src = load_idx(eidx, e);
    int dst = load_idx(eidx, E + e);
    int pos = atomicAdd(&g_cursor[dst], 1);
    g_csr_src[pos] = src;
}

// ---------------- row GEMM with packed f32x2 FMA, pre-packed W operands ----------------
template<int K>
__global__ void __launch_bounds__(128) k_gemm(const float* __restrict__ A,
                                              const float* __restrict__ W,
                                              const float* __restrict__ bias,
                                              const float* __restrict__ isq,
                                              float* __restrict__ out, int n) {
    __shared__ ulonglong2 Ws[K * 16];   // K rows x 64 floats, as packed f32x2 pairs
    __shared__ float      As[128 * 17]; // 128 nodes x 16 k, padded

    for (int i = threadIdx.x; i < K * 16; i += 128)
        Ws[i] = reinterpret_cast<const ulonglong2*>(W)[i];

    unsigned long long acc[32];
#pragma unroll
    for (int j = 0; j < 32; j++) acc[j] = 0ULL;

    int node = blockIdx.x * 128 + threadIdx.x;

    for (int k0 = 0; k0 < K; k0 += 16) {
        __syncthreads();
#pragma unroll
        for (int i = 0; i < 16; i++) {
            int idx = i * 128 + threadIdx.x;
            int nn = idx >> 4, kk = idx & 15;
            int gn = blockIdx.x * 128 + nn;
            As[nn * 17 + kk] = (gn < n) ? A[(size_t)gn * K + k0 + kk] : 0.f;
        }
        __syncthreads();
#pragma unroll
        for (int kk = 0; kk < 16; kk++) {
            float a = As[threadIdx.x * 17 + kk];
            unsigned long long a2;
            asm("mov.b64 %0, {%1, %1};" : "=l"(a2) : "f"(a));
            const ulonglong2* wr = &Ws[(k0 + kk) * 16];
#pragma unroll
            for (int j = 0; j < 16; j++) {
                ulonglong2 w = wr[j];
                asm("fma.rn.f32x2 %0, %1, %2, %0;" : "+l"(acc[2 * j])     : "l"(a2), "l"(w.x));
                asm("fma.rn.f32x2 %0, %1, %2, %0;" : "+l"(acc[2 * j + 1]) : "l"(a2), "l"(w.y));
            }
        }
    }

    if (node < n) {
        float s = isq ? isq[node] : 1.0f;
        float2* o = reinterpret_cast<float2*>(out) + (size_t)node * 32;
#pragma unroll
        for (int j = 0; j < 32; j++) {
            float lo, hi;
            asm("mov.b64 {%0, %1}, %2;" : "=f"(lo), "=f"(hi) : "l"(acc[j]));
            if (bias) {
                float2 b = reinterpret_cast<const float2*>(bias)[j];
                lo += b.x; hi += b.y;
            }
            o[j] = make_float2(lo * s, hi * s);
        }
    }
}

// ---------------- fused gather + self + bias + LN + ReLU (+skip+readout) ----------------
// One warp per node, 4-deep load pipelining.
__global__ void __launch_bounds__(256) k_gather(const float* __restrict__ bias,
                                                const float* __restrict__ lng,
                                                const float* __restrict__ lnb,
                                                float* __restrict__ outh, int n,
                                                int do_readout,
                                                const void* __restrict__ batch) {
    int t = blockIdx.x * blockDim.x + threadIdx.x;
    int node = t >> 5, lane = t & 31;
    if (node >= n) return;

    int start = g_ptr[node];
    int cnt   = g_cnt[node];
    size_t off = (size_t)node * 32 + lane;
    const float2* hws2 = (const float2*)g_hws;

    float2 a0 = __ldg(&hws2[off]);  // self-loop term
    float2 a1 = make_float2(0.f, 0.f);
    float2 a2 = make_float2(0.f, 0.f);
    float2 a3 = make_float2(0.f, 0.f);

    int j = 0;
    for (; j + 3 < cnt; j += 4) {
        int s0 = __ldg(&g_csr_src[start + j]);
        int s1 = __ldg(&g_csr_src[start + j + 1]);
        int s2 = __ldg(&g_csr_src[start + j + 2]);
        int s3 = __ldg(&g_csr_src[start + j + 3]);
        float2 v0 = __ldg(&hws2[(size_t)s0 * 32 + lane]);
        float2 v1 = __ldg(&hws2[(size_t)s1 * 32 + lane]);
        float2 v2 = __ldg(&hws2[(size_t)s2 * 32 + lane]);
        float2 v3 = __ldg(&hws2[(size_t)s3 * 32 + lane]);
        a0.x += v0.x; a0.y += v0.y;
        a1.x += v1.x; a1.y += v1.y;
        a2.x += v2.x; a2.y += v2.y;
        a3.x += v3.x; a3.y += v3.y;
    }
    for (; j < cnt; j++) {
        int s0 = __ldg(&g_csr_src[start + j]);
        float2 v = __ldg(&hws2[(size_t)s0 * 32 + lane]);
        a0.x += v.x; a0.y += v.y;
    }

    float s = g_deg[node];  // isq
    float2 bb = ((const float2*)bias)[lane];
    float vx = fmaf(s, (a0.x + a1.x) + (a2.x + a3.x), bb.x);
    float vy = fmaf(s, (a0.y + a1.y) + (a2.y + a3.y), bb.y);

    float sum = vx + vy;
#pragma unroll
    for (int o = 16; o; o >>= 1) sum += __shfl_xor_sync(0xffffffffu, sum, o);
    float mu = sum * (1.0f / 64.0f);

    float dx = vx - mu, dy = vy - mu;
    float var = dx * dx + dy * dy;
#pragma unroll
    for (int o = 16; o; o >>= 1) var += __shfl_xor_sync(0xffffffffu, var, o);
    float rstd = rsqrtf(var * (1.0f / 64.0f) + 1e-5f);

    float2 gg = ((const float2*)lng)[lane];
    float2 lb = ((const float2*)lnb)[lane];
    float ox = fmaxf(fmaf(dx * rstd, gg.x, lb.x), 0.f);
    float oy = fmaxf(fmaf(dy * rstd, gg.y, lb.y), 0.f);

    if (!do_readout) {
        ((float2*)outh)[off] = make_float2(ox, oy);
    } else {
        float2 h1v = ((const float2*)g_h1)[off];
        float2 sk = make_float2(ox + h1v.x, oy + h1v.y);
        int grp = load_idx(batch, node);
        atomicAdd(((float2*)g_readout) + (size_t)grp * 32 + lane, sk);
    }
}

// ---------------- post GEMM ----------------
__global__ void k_post(const float* __restrict__ W, const float* __restrict__ b,
                       float* __restrict__ out, int G) {
    __shared__ float r[64];
    int g = blockIdx.x;
    r[threadIdx.x] = g_readout[(size_t)g * 64 + threadIdx.x];
    __syncthreads();
    int c = threadIdx.x;
    if (c < 40) {
        float acc = b[c];
#pragma unroll
        for (int k = 0; k < 64; k++) acc = fmaf(r[k], __ldg(&W[k * 40 + c]), acc);
        out[(size_t)g * 40 + c] = acc;
    }
}

// ---------------- launch (forked streams, capture-safe fork/join) ----------------
extern "C" void kernel_launch(void* const* d_in, const int* in_sizes, int n_in,
                              void* d_out, int out_size) {
    const float* x      = (const float*)d_in[0];
    const void*  eidx   = d_in[1];
    const void*  batch  = d_in[2];
    const float* pre_w  = (const float*)d_in[3];
    const float* pre_b  = (const float*)d_in[4];
    const float* c1_w   = (const float*)d_in[5];
    const float* c1_b   = (const float*)d_in[6];
    const float* n1_g   = (const float*)d_in[7];
    const float* n1_b   = (const float*)d_in[8];
    const float* c2_w   = (const float*)d_in[9];
    const float* c2_b   = (const float*)d_in[10];
    const float* n2_g   = (const float*)d_in[11];
    const float* n2_b   = (const float*)d_in[12];
    const float* post_w = (const float*)d_in[13];
    const float* post_b = (const float*)d_in[14];

    int N = in_sizes[0] / 128;
    int E = in_sizes[1] / 2;
    int G = out_size / 40;

    float *p_h, *p_hws, *p_h1, *p_isq;
    cudaGetSymbolAddress((void**)&p_h,   g_h);
    cudaGetSymbolAddress((void**)&p_hws, g_hws);
    cudaGetSymbolAddress((void**)&p_h1,  g_h1);
    cudaGetSymbolAddress((void**)&p_isq, g_deg);

    // One-time resource creation (no device memory; identical captured work per call).
    static cudaStream_t s1 = nullptr, s2 = nullptr;
    static cudaEvent_t evFork = nullptr, evIsq = nullptr, evGemm = nullptr, evCsr = nullptr;
    if (!s1) {
        cudaStreamCreateWithFlags(&s1, cudaStreamNonBlocking);
        cudaStreamCreateWithFlags(&s2, cudaStreamNonBlocking);
        cudaEventCreateWithFlags(&evFork, cudaEventDisableTiming);
        cudaEventCreateWithFlags(&evIsq,  cudaEventDisableTiming);
        cudaEventCreateWithFlags(&evGemm, cudaEventDisableTiming);
        cudaEventCreateWithFlags(&evCsr,  cudaEventDisableTiming);
    }

    int dcnt = 2 * E < 1024 ? 2 * E : 1024;
    k_detect<<<1, 1024>>>((const long long*)eidx, dcnt, (long long)N);
    cudaEventRecord(evFork, 0);
    cudaStreamWaitEvent(s1, evFork, 0);
    cudaStreamWaitEvent(s2, evFork, 0);

    // --- s2: CSR build branch ---
    int zmax = (N > G * 16) ? N : G * 16;
    k_zero<<<(zmax + 255) / 256, 256, 0, s2>>>(N, G);
    k_hist<<<(E + 255) / 256, 256, 0, s2>>>(eidx, E);
    int nb = (N + 1023) / 1024;
    k_scan1<<<nb, 256, 0, s2>>>(N);
    k_scan2<<<1, 128, 0, s2>>>(nb);
    k_scan3<<<(N + 255) / 256, 256, 0, s2>>>(N);   // produces isq
    cudaEventRecord(evIsq, s2);
    k_fill<<<(E + 255) / 256, 256, 0, s2>>>(eidx, E);
    cudaEventRecord(evCsr, s2);

    // --- s1: GEMM branch ---
    k_gemm<128><<<(N + 127) / 128, 128, 0, s1>>>(x, pre_w, pre_b, nullptr, p_h, N);
    cudaStreamWaitEvent(s1, evIsq, 0);             // gemm1 needs isq
    k_gemm<64><<<(N + 127) / 128, 128, 0, s1>>>(p_h, c1_w, nullptr, p_isq, p_hws, N);
    cudaEventRecord(evGemm, s1);

    // --- join on origin stream ---
    cudaStreamWaitEvent(0, evGemm, 0);
    cudaStreamWaitEvent(0, evCsr, 0);

    // layer 1: fused gather+LN+ReLU -> h1
    k_gather<<<((size_t)N * 32 + 255) / 256, 256>>>(c1_b, n1_g, n1_b, p_h1, N, 0, nullptr);

    // layer 2: fused gather+LN+ReLU+skip+readout pooling
    k_gemm<64><<<(N + 127) / 128, 128>>>(p_h1, c2_w, nullptr, p_isq, p_hws, N);
    k_gather<<<((size_t)N * 32 + 255) / 256, 256>>>(c2_b, n2_g, n2_b, nullptr, N, 1, batch);

    // post: out = readout @ post_w + post_b
    k_post<<<G, 64>>>(post_w, post_b, (float*)d_out, G);
}